// round 12
// baseline (speedup 1.0000x reference)
#include <cuda_runtime.h>

#define N_POINTS 65536
#define N_GAUSS  1024
#define GSPLIT   16
#define GCHUNK   (N_GAUSS / GSPLIT)     // 64 gaussians per block chunk
#define BLOCK    128
#define PPT      8                      // points (slots) per thread
#define PTILE    (BLOCK * PPT)          // 1024 slots per block
#define NPT      (N_POINTS / PTILE)     // 64 slot tiles -> grid 64x16 = 1024 blocks
#define NCELL    512                    // 8x8x8 spatial grid over [-4,4]^3
#define NWORD    (N_GAUSS / 32)         // 32 mask words per cell
#define QCUT     34.0f                  // drop weights below 2^-34

// Per-gaussian fused params, 12 floats (48 B = 3 x float4):
// [u00 u01 u02 k0 | u11 u12 k1 u22 | k2 na pad pad]
// M = sqrt(0.5*log2 e)*diag(1/s)*R; Givens-QR M = Q U => e = na - |U p + k|^2,
// contribution = 2^e, na = log2(alpha) - 10 (folds the /1024 mean).
__device__ float4   g_gauss[N_GAUSS * 3];
__device__ unsigned g_mask[NCELL][NWORD];      // bit=1 -> evaluate for this cell
__device__ unsigned g_hist[NCELL];
__device__ unsigned g_start[NCELL + 1];
__device__ unsigned g_cursor[NCELL];
__device__ float4   g_pts[N_POINTS];           // sorted points (x,y,z,0)
__device__ int      g_perm[N_POINTS];          // slot -> original point id
__device__ int      g_slotcell[N_POINTS];      // slot -> cell id (deterministic)
__device__ float    g_partial[GSPLIT][N_POINTS];
__device__ unsigned g_ticket[NPT];             // monotonic; replay-safe via modulo

__device__ __forceinline__ float ex2f(float e) {
    float r; asm("ex2.approx.ftz.f32 %0, %1;" : "=f"(r) : "f"(e)); return r;
}
__device__ __forceinline__ int cell_of(float x, float y, float z) {
    int ix = min(7, max(0, (int)floorf(x + 4.f)));
    int iy = min(7, max(0, (int)floorf(y + 4.f)));
    int iz = min(7, max(0, (int)floorf(z + 4.f)));
    return ix + (iy << 3) + (iz << 6);
}

// ---- fp32 Givens QR precompute: one gaussian per thread ----
__global__ void precompute_kernel(const float* __restrict__ centers,
                                  const float* __restrict__ angles,
                                  const float* __restrict__ scales,
                                  const float* __restrict__ alphas) {
    int m = blockIdx.x * blockDim.x + threadIdx.x;
    if (m >= N_GAUSS) return;

    float sx, cx, sy, cy, sz, cz;
    sincospif(angles[3 * m + 0], &sx, &cx);     // deg2rad(a*180) = a*pi
    sincospif(angles[3 * m + 1], &sy, &cy);
    sincospif(angles[3 * m + 2], &sz, &cz);

    float r00 = cz * cy;
    float r01 = cz * sy * sx - sz * cx;
    float r02 = cz * sy * cx + sz * sx;
    float r10 = sz * cy;
    float r11 = sz * sy * sx + cz * cx;
    float r12 = sz * sy * cx - cz * sx;
    float r20 = -sy;
    float r21 = cy * sx;
    float r22 = cy * cx;

    const float K = 0.84934163f;   // sqrt(0.5 * log2(e))
    float i0 = K / scales[3 * m + 0];
    float i1 = K / scales[3 * m + 1];
    float i2 = K / scales[3 * m + 2];

    float a0 = r00 * i0, a1 = r01 * i0, a2 = r02 * i0;
    float b0 = r10 * i1, b1 = r11 * i1, b2 = r12 * i1;
    float g0 = r20 * i2, g1 = r21 * i2, g2 = r22 * i2;

    {   // rot(0,1) zero b0
        float rr = fmaf(a0, a0, b0 * b0);
        float cc = 1.f, ss = 0.f;
        if (rr > 1e-30f) { float inv = rsqrtf(rr); cc = a0 * inv; ss = b0 * inv; }
        float n0 = fmaf(cc, a0, ss * b0);
        float n1 = fmaf(cc, a1, ss * b1);
        float n2 = fmaf(cc, a2, ss * b2);
        float q1 = fmaf(cc, b1, -ss * a1);
        float q2 = fmaf(cc, b2, -ss * a2);
        a0 = n0; a1 = n1; a2 = n2; b1 = q1; b2 = q2;
    }
    {   // rot(0,2) zero g0
        float rr = fmaf(a0, a0, g0 * g0);
        float cc = 1.f, ss = 0.f;
        if (rr > 1e-30f) { float inv = rsqrtf(rr); cc = a0 * inv; ss = g0 * inv; }
        float n0 = fmaf(cc, a0, ss * g0);
        float n1 = fmaf(cc, a1, ss * g1);
        float n2 = fmaf(cc, a2, ss * g2);
        float q1 = fmaf(cc, g1, -ss * a1);
        float q2 = fmaf(cc, g2, -ss * a2);
        a0 = n0; a1 = n1; a2 = n2; g1 = q1; g2 = q2;
    }
    {   // rot(1,2) zero g1
        float rr = fmaf(b1, b1, g1 * g1);
        float cc = 1.f, ss = 0.f;
        if (rr > 1e-30f) { float inv = rsqrtf(rr); cc = b1 * inv; ss = g1 * inv; }
        float n1 = fmaf(cc, b1, ss * g1);
        float n2 = fmaf(cc, b2, ss * g2);
        float q2 = fmaf(cc, g2, -ss * b2);
        b1 = n1; b2 = n2; g2 = q2;
    }

    float cx0 = centers[3 * m + 0];
    float cy0 = centers[3 * m + 1];
    float cz0 = centers[3 * m + 2];
    float k0 = -fmaf(a0, cx0, fmaf(a1, cy0, a2 * cz0));
    float k1 = -fmaf(b1, cy0, b2 * cz0);
    float k2 = -(g2 * cz0);
    float na = log2f(alphas[m]) - 10.0f;

    g_gauss[3 * m + 0] = make_float4(a0, a1, a2, k0);
    g_gauss[3 * m + 1] = make_float4(b1, b2, k1, g2);
    g_gauss[3 * m + 2] = make_float4(k2, na, 0.f, 0.f);
}

// ---- per-(cell, 32-gaussian word) conservative cull mask ----
__global__ void mask_kernel() {
    int t = blockIdx.x * blockDim.x + threadIdx.x;   // 512*32 = 16384 threads
    if (t >= NCELL * NWORD) return;
    int cell = t >> 5;
    int word = t & 31;

    int ix = cell & 7, iy = (cell >> 3) & 7, iz = cell >> 6;
    float lox = -4.f + ix, hix = lox + 1.f;
    float loy = -4.f + iy, hiy = loy + 1.f;
    float loz = -4.f + iz, hiz = loz + 1.f;
    if (ix == 0) lox = -100.f;  if (ix == 7) hix = 100.f;
    if (iy == 0) loy = -100.f;  if (iy == 7) hiy = 100.f;
    if (iz == 0) loz = -100.f;  if (iz == 7) hiz = 100.f;
    float wx = 0.5f * (lox + hix), hx = 0.5f * (hix - lox);
    float wy = 0.5f * (loy + hiy), hy = 0.5f * (hiy - loy);
    float wz = 0.5f * (loz + hiz), hz = 0.5f * (hiz - loz);

    unsigned bits = 0;
    for (int gl = 0; gl < 32; gl++) {
        int g = word * 32 + gl;
        float4 p0 = g_gauss[3 * g + 0];
        float4 p1 = g_gauss[3 * g + 1];
        float4 p2 = g_gauss[3 * g + 2];
        float t0 = fmaf(p0.x, wx, fmaf(p0.y, wy, fmaf(p0.z, wz, p0.w)));
        float t1 = fmaf(p1.x, wy, fmaf(p1.y, wz, p1.z));
        float t2 = fmaf(p1.w, wz, p2.x);
        float rho0 = fmaf(fabsf(p0.x), hx, fmaf(fabsf(p0.y), hy, fabsf(p0.z) * hz));
        float rho1 = fmaf(fabsf(p1.x), hy, fabsf(p1.y) * hz);
        float rho2 = fabsf(p1.w) * hz;
        float d0 = fmaxf(fabsf(t0) - rho0, 0.f);
        float d1 = fmaxf(fabsf(t1) - rho1, 0.f);
        float d2 = fmaxf(fabsf(t2) - rho2, 0.f);
        float qmin = fmaf(d0, d0, fmaf(d1, d1, d2 * d2));
        if (qmin <= p2.y + QCUT) bits |= (1u << gl);   // p2.y = na
    }
    g_mask[cell][word] = bits;
}

// ---- spatial binning: histogram (smem-local then merge) ----
__global__ void hist_kernel(const float* __restrict__ points) {
    __shared__ unsigned sh[NCELL];
    for (int i = threadIdx.x; i < NCELL; i += blockDim.x) sh[i] = 0;
    __syncthreads();
    int i = blockIdx.x * blockDim.x + threadIdx.x;
    float x = points[3 * i], y = points[3 * i + 1], z = points[3 * i + 2];
    atomicAdd(&sh[cell_of(x, y, z)], 1u);
    __syncthreads();
    for (int c = threadIdx.x; c < NCELL; c += blockDim.x)
        if (sh[c]) atomicAdd(&g_hist[c], sh[c]);
}

// ---- exclusive scan of 512 counters (single block) ----
__global__ void scan_kernel() {
    __shared__ unsigned s[NCELL];
    int t = threadIdx.x;
    unsigned own = g_hist[t];
    s[t] = own;
    __syncthreads();
    for (int st = 1; st < NCELL; st <<= 1) {
        unsigned add = (t >= st) ? s[t - st] : 0u;
        __syncthreads();
        s[t] += add;
        __syncthreads();
    }
    unsigned excl = s[t] - own;
    g_start[t] = excl;
    g_cursor[t] = excl;
    if (t == NCELL - 1) g_start[NCELL] = s[NCELL - 1];
}

// ---- scatter points into sorted slots ----
__global__ void scatter_kernel(const float* __restrict__ points) {
    int i = blockIdx.x * blockDim.x + threadIdx.x;
    float x = points[3 * i], y = points[3 * i + 1], z = points[3 * i + 2];
    int c = cell_of(x, y, z);
    int slot = (int)atomicAdd(&g_cursor[c], 1u);
    g_pts[slot] = make_float4(x, y, z, 0.f);
    g_perm[slot] = i;
    g_slotcell[slot] = c;   // deterministic: determined by g_start ranges
}

// ---- main eval: masked gaussian loop over sorted points ----
__global__ void __launch_bounds__(BLOCK) eval_kernel(float* __restrict__ out) {
    __shared__ __align__(16) float4 sg[GCHUNK * 3];   // 3 KB
    __shared__ unsigned s_ticket;

    {
        const float4* src = &g_gauss[blockIdx.y * GCHUNK * 3];
        for (int i = threadIdx.x; i < GCHUNK * 3; i += BLOCK) sg[i] = src[i];
    }

    int warp = threadIdx.x >> 5, lane = threadIdx.x & 31;
    int wslot = blockIdx.x * PTILE + warp * 256;   // warp owns 256 contiguous slots
    int base2 = wslot + lane * 2;                  // this thread: base2+j*64+{0,1}

    // combined evaluate-mask over the warp's covered cells (2 words for GCHUNK=64)
    int c0 = g_slotcell[wslot];
    int c1 = g_slotcell[wslot + 255];
    int wi = blockIdx.y * 2;
    unsigned a = 0, b = 0;
    for (int c = c0 + lane; c <= c1; c += 32) {
        a |= g_mask[c][wi];
        b |= g_mask[c][wi + 1];
    }
    unsigned m0 = __reduce_or_sync(0xffffffffu, a);
    unsigned m1 = __reduce_or_sync(0xffffffffu, b);

    float px[PPT], py[PPT], pz[PPT], acc[PPT];
#pragma unroll
    for (int j = 0; j < PPT / 2; j++) {
        int idx = base2 + j * 64;
        float4 A = g_pts[idx];
        float4 B = g_pts[idx + 1];
        px[2 * j + 0] = A.x; py[2 * j + 0] = A.y; pz[2 * j + 0] = A.z;
        px[2 * j + 1] = B.x; py[2 * j + 1] = B.y; pz[2 * j + 1] = B.z;
        acc[2 * j + 0] = 0.f; acc[2 * j + 1] = 0.f;
    }
    __syncthreads();

#pragma unroll 1
    for (int m = 0; m < GCHUNK; m++) {
        unsigned mk = (m < 32) ? m0 : m1;
        if ((mk >> (m & 31)) & 1u) {
            float4 w0 = sg[3 * m + 0];
            float4 w1 = sg[3 * m + 1];
            float4 w2 = sg[3 * m + 2];
            float u00 = w0.x, u01 = w0.y, u02 = w0.z, k0 = w0.w;
            float u11 = w1.x, u12 = w1.y, k1 = w1.z, u22 = w1.w;
            float k2 = w2.x, na = w2.y;
#pragma unroll
            for (int j = 0; j < PPT; j++) {
                float t0 = fmaf(u00, px[j], fmaf(u01, py[j], fmaf(u02, pz[j], k0)));
                float t1 = fmaf(u11, py[j], fmaf(u12, pz[j], k1));
                float t2 = fmaf(u22, pz[j], k2);
                float e = fmaf(t0, -t0, fmaf(t1, -t1, fmaf(t2, -t2, na)));
                acc[j] += ex2f(e);
            }
        }
    }

    float* part = g_partial[blockIdx.y];
#pragma unroll
    for (int j = 0; j < PPT / 2; j++) {
        int idx = base2 + j * 64;
        *reinterpret_cast<float2*>(part + idx) = make_float2(acc[2 * j + 0], acc[2 * j + 1]);
    }

    // deterministic last-block combine (ticket monotonic -> replay safe)
    __threadfence();
    __syncthreads();
    if (threadIdx.x == 0) s_ticket = atomicAdd(&g_ticket[blockIdx.x], 1u);
    __syncthreads();
    if ((s_ticket & (GSPLIT - 1)) == GSPLIT - 1) {
        __threadfence();
#pragma unroll
        for (int j = 0; j < PPT / 2; j++) {
            int idx = base2 + j * 64;
            float s0 = 0.f, s1 = 0.f;
#pragma unroll
            for (int g = 0; g < GSPLIT; g++) {   // fixed order -> deterministic sum
                const float2* pp = reinterpret_cast<const float2*>(&g_partial[g][idx]);
                float2 v = __ldcg(pp);
                s0 += v.x; s1 += v.y;
            }
            out[g_perm[idx]]     = s0;
            out[g_perm[idx + 1]] = s1;
        }
    }
}

extern "C" void kernel_launch(void* const* d_in, const int* in_sizes, int n_in,
                              void* d_out, int out_size) {
    const float* points  = (const float*)d_in[0];
    const float* centers = (const float*)d_in[1];
    const float* angles  = (const float*)d_in[2];
    const float* scales  = (const float*)d_in[3];
    const float* alphas  = (const float*)d_in[4];
    float* out = (float*)d_out;

    void* hist_ptr = nullptr;
    cudaGetSymbolAddress(&hist_ptr, g_hist);
    cudaMemsetAsync(hist_ptr, 0, NCELL * sizeof(unsigned), 0);

    precompute_kernel<<<8, 128>>>(centers, angles, scales, alphas);
    mask_kernel<<<64, 256>>>();
    hist_kernel<<<N_POINTS / 256, 256>>>(points);
    scan_kernel<<<1, NCELL>>>();
    scatter_kernel<<<N_POINTS / 256, 256>>>(points);

    dim3 grid(NPT, GSPLIT);
    eval_kernel<<<grid, BLOCK>>>(out);
}

// round 13
// speedup vs baseline: 2.0000x; 2.0000x over previous
#include <cuda_runtime.h>

#define N_POINTS 65536
#define N_GAUSS  1024
#define GSPLIT   16
#define GCHUNK   (N_GAUSS / GSPLIT)     // 64 gaussians per block chunk
#define BLOCK    128
#define PPT      8                      // points per thread
#define PTILE    (BLOCK * PPT)          // 1024 points per block
#define NPT      (N_POINTS / PTILE)     // 64 point tiles -> grid 64x16 = 1024 blocks

// Per-gaussian fused params, 12 floats (48 B = 3 x float4), built IN-BLOCK:
// [u00 u01 u02 k0 | u11 u12 k1 u22 | k2 na pad pad]
// M = sqrt(0.5*log2 e)*diag(1/s)*R; Givens-QR M = Q U => q_log2 = |U p + k|^2,
// k = -U c.  contribution = 2^e,  e = na - t0^2 - t1^2 - t2^2,
// na = log2(alpha) - 10   (folds the /1024 mean into the exponent).
__device__ float g_partial[GSPLIT][N_POINTS];
__device__ unsigned g_ticket[NPT];      // monotonic; replay-safe via modulo test

__device__ __forceinline__ float ex2f(float e) {
    float r; asm("ex2.approx.ftz.f32 %0, %1;" : "=f"(r) : "f"(e)); return r;
}

__global__ void __launch_bounds__(BLOCK) eval_kernel(const float* __restrict__ points,
                                                     const float* __restrict__ centers,
                                                     const float* __restrict__ angles,
                                                     const float* __restrict__ scales,
                                                     const float* __restrict__ alphas,
                                                     float* __restrict__ out) {
    __shared__ __align__(16) float4 sg[GCHUNK * 3];   // 3 KB
    __shared__ unsigned s_ticket;

    // ---- load this thread's 8 points first (LDG latency overlaps the QR below) ----
    int base = blockIdx.x * PTILE + threadIdx.x * 2;
    float px[PPT], py[PPT], pz[PPT], acc[PPT];
#pragma unroll
    for (int j = 0; j < PPT / 2; j++) {
        int idx = base + j * (BLOCK * 2);
        const float2* p = reinterpret_cast<const float2*>(points + 3 * idx);
        float2 f0 = p[0], f1 = p[1], f2 = p[2];   // x0 y0 | z0 x1 | y1 z1
        px[2 * j + 0] = f0.x; py[2 * j + 0] = f0.y; pz[2 * j + 0] = f1.x;
        px[2 * j + 1] = f1.y; py[2 * j + 1] = f2.x; pz[2 * j + 1] = f2.y;
        acc[2 * j + 0] = 0.f; acc[2 * j + 1] = 0.f;
    }

    // ---- in-block precompute: threads 0..63 each QR one gaussian of this chunk ----
    if (threadIdx.x < GCHUNK) {
        int m = blockIdx.y * GCHUNK + threadIdx.x;

        float sx, cx, sy, cy, sz, cz;
        sincospif(angles[3 * m + 0], &sx, &cx);     // deg2rad(a*180) = a*pi
        sincospif(angles[3 * m + 1], &sy, &cy);
        sincospif(angles[3 * m + 2], &sz, &cz);

        // R = Rz @ Ry @ Rx
        float r00 = cz * cy;
        float r01 = cz * sy * sx - sz * cx;
        float r02 = cz * sy * cx + sz * sx;
        float r10 = sz * cy;
        float r11 = sz * sy * sx + cz * cx;
        float r12 = sz * sy * cx - cz * sx;
        float r20 = -sy;
        float r21 = cy * sx;
        float r22 = cy * cx;

        const float K = 0.84934163f;   // sqrt(0.5 * log2(e))
        float i0 = K / scales[3 * m + 0];
        float i1 = K / scales[3 * m + 1];
        float i2 = K / scales[3 * m + 2];

        float a0 = r00 * i0, a1 = r01 * i0, a2 = r02 * i0;    // row 0
        float b0 = r10 * i1, b1 = r11 * i1, b2 = r12 * i1;    // row 1
        float g0 = r20 * i2, g1 = r21 * i2, g2 = r22 * i2;    // row 2

        // rot(0,1) zero b0
        {
            float rr = fmaf(a0, a0, b0 * b0);
            float cc = 1.f, ss = 0.f;
            if (rr > 1e-30f) { float inv = rsqrtf(rr); cc = a0 * inv; ss = b0 * inv; }
            float n0 = fmaf(cc, a0, ss * b0);
            float n1 = fmaf(cc, a1, ss * b1);
            float n2 = fmaf(cc, a2, ss * b2);
            float q1 = fmaf(cc, b1, -ss * a1);
            float q2 = fmaf(cc, b2, -ss * a2);
            a0 = n0; a1 = n1; a2 = n2; b1 = q1; b2 = q2;
        }
        // rot(0,2) zero g0
        {
            float rr = fmaf(a0, a0, g0 * g0);
            float cc = 1.f, ss = 0.f;
            if (rr > 1e-30f) { float inv = rsqrtf(rr); cc = a0 * inv; ss = g0 * inv; }
            float n0 = fmaf(cc, a0, ss * g0);
            float n1 = fmaf(cc, a1, ss * g1);
            float n2 = fmaf(cc, a2, ss * g2);
            float q1 = fmaf(cc, g1, -ss * a1);
            float q2 = fmaf(cc, g2, -ss * a2);
            a0 = n0; a1 = n1; a2 = n2; g1 = q1; g2 = q2;
        }
        // rot(1,2) zero g1 (components 1,2 only)
        {
            float rr = fmaf(b1, b1, g1 * g1);
            float cc = 1.f, ss = 0.f;
            if (rr > 1e-30f) { float inv = rsqrtf(rr); cc = b1 * inv; ss = g1 * inv; }
            float n1 = fmaf(cc, b1, ss * g1);
            float n2 = fmaf(cc, b2, ss * g2);
            float q2 = fmaf(cc, g2, -ss * b2);
            b1 = n1; b2 = n2; g2 = q2;
        }
        // U = [a0 a1 a2; 0 b1 b2; 0 0 g2]

        float cx0 = centers[3 * m + 0];
        float cy0 = centers[3 * m + 1];
        float cz0 = centers[3 * m + 2];
        float k0 = -fmaf(a0, cx0, fmaf(a1, cy0, a2 * cz0));
        float k1 = -fmaf(b1, cy0, b2 * cz0);
        float k2 = -(g2 * cz0);
        float na = log2f(alphas[m]) - 10.0f;   // alpha==0 -> -inf -> 2^e = 0 (correct)

        sg[3 * threadIdx.x + 0] = make_float4(a0, a1, a2, k0);
        sg[3 * threadIdx.x + 1] = make_float4(b1, b2, k1, g2);
        sg[3 * threadIdx.x + 2] = make_float4(k2, na, 0.f, 0.f);
    }
    __syncthreads();

    // ---- main loop: 64 gaussians x 8 points, 11 issue-slots per point ----
#pragma unroll 2
    for (int m = 0; m < GCHUNK; m++) {
        float4 w0 = sg[3 * m + 0];
        float4 w1 = sg[3 * m + 1];
        float4 w2 = sg[3 * m + 2];
        float u00 = w0.x, u01 = w0.y, u02 = w0.z, k0 = w0.w;
        float u11 = w1.x, u12 = w1.y, k1 = w1.z, u22 = w1.w;
        float k2 = w2.x, na = w2.y;
#pragma unroll
        for (int j = 0; j < PPT; j++) {
            float t0 = fmaf(u00, px[j], fmaf(u01, py[j], fmaf(u02, pz[j], k0)));
            float t1 = fmaf(u11, py[j], fmaf(u12, pz[j], k1));
            float t2 = fmaf(u22, pz[j], k2);
            // e = na - t0^2 - t1^2 - t2^2 : negation folded into FFMA src modifiers
            float e = fmaf(t0, -t0, fmaf(t1, -t1, fmaf(t2, -t2, na)));
            acc[j] += ex2f(e);
        }
    }

    // ---- write this chunk's partial ----
    float* part = g_partial[blockIdx.y];
#pragma unroll
    for (int j = 0; j < PPT / 2; j++) {
        int idx = base + j * (BLOCK * 2);
        *reinterpret_cast<float2*>(part + idx) = make_float2(acc[2 * j + 0], acc[2 * j + 1]);
    }

    // ---- deterministic last-block combine (ticket monotonic -> replay safe) ----
    __threadfence();
    __syncthreads();
    if (threadIdx.x == 0) s_ticket = atomicAdd(&g_ticket[blockIdx.x], 1u);
    __syncthreads();
    if ((s_ticket & (GSPLIT - 1)) == GSPLIT - 1) {
        __threadfence();
#pragma unroll
        for (int j = 0; j < PPT / 2; j++) {
            int idx = base + j * (BLOCK * 2);
            float s0 = 0.f, s1 = 0.f;
#pragma unroll
            for (int g = 0; g < GSPLIT; g++) {      // fixed order -> bitwise deterministic
                const float2* pp = reinterpret_cast<const float2*>(&g_partial[g][idx]);
                float2 v = __ldcg(pp);
                s0 += v.x; s1 += v.y;
            }
            *reinterpret_cast<float2*>(out + idx) = make_float2(s0, s1);
        }
    }
}

extern "C" void kernel_launch(void* const* d_in, const int* in_sizes, int n_in,
                              void* d_out, int out_size) {
    const float* points  = (const float*)d_in[0];
    const float* centers = (const float*)d_in[1];
    const float* angles  = (const float*)d_in[2];
    const float* scales  = (const float*)d_in[3];
    const float* alphas  = (const float*)d_in[4];
    float* out = (float*)d_out;

    dim3 grid(NPT, GSPLIT);
    eval_kernel<<<grid, BLOCK>>>(points, centers, angles, scales, alphas, out);
}